// round 2
// baseline (speedup 1.0000x reference)
#include <cuda_runtime.h>
#include <cuda_bf16.h>

// Problem constants
#define Bz   8
#define Cc   512
#define Hh   96
#define Ww   96
#define HWp  9216           // H*W
#define NPIX (Bz * HWp)     // 73728
#define CKV  64

// Scratch (device globals: allocation-free per harness rules)
__device__ float g_k1[Bz * CKV * HWp];   // relu(key1 conv)
__device__ float g_v [Bz * CKV * HWp];   // value conv
__device__ float g_ws[Bz * 9   * HWp];   // softmax tap weights
__device__ float g_y [Bz * CKV * HWp];   // weighted neighborhood sum

// ---------------------------------------------------------------------------
// Kernel 1: fused key1 + value 1x1 convs as a 128x128-tile SGEMM.
//   out[o, p] = sum_k W[o,k] * x[k,p]; o in [0,64)=key1(+ReLU), [64,128)=value
//   grid.x = NPIX/128 = 576, block = 256
// ---------------------------------------------------------------------------
__global__ __launch_bounds__(256) void k1v_gemm(
    const float* __restrict__ x,
    const float* __restrict__ k1w, const float* __restrict__ k1b,
    const float* __restrict__ vw,  const float* __restrict__ vb)
{
    __shared__ float sW[16][128];
    __shared__ float sX[16][128];

    const int pt  = blockIdx.x;
    const int b   = pt / 72;              // HW/128 = 72 pixel tiles per image
    const int hw0 = (pt % 72) * 128;
    const float* xb = x + (size_t)b * Cc * HWp + hw0;

    const int t  = threadIdx.x;
    const int ty = t >> 4;
    const int tx = t & 15;

    float acc[8][8];
    #pragma unroll
    for (int i = 0; i < 8; i++)
        #pragma unroll
        for (int j = 0; j < 8; j++) acc[i][j] = 0.f;

    for (int k0 = 0; k0 < Cc; k0 += 16) {
        // Load weight tile: 128 out-ch x 16 k  (512 float4, 2 per thread)
        #pragma unroll
        for (int i = 0; i < 2; i++) {
            int lin = t * 2 + i;                   // 0..511
            int o   = lin >> 2;                    // 0..127
            int kq  = lin & 3;                     // 0..3 (float4 within 16 k)
            const float* wrow = (o < 64) ? (k1w + (size_t)o * Cc)
                                         : (vw  + (size_t)(o - 64) * Cc);
            float4 w4 = *(const float4*)(wrow + k0 + kq * 4);
            sW[kq*4+0][o] = w4.x; sW[kq*4+1][o] = w4.y;
            sW[kq*4+2][o] = w4.z; sW[kq*4+3][o] = w4.w;
        }
        // Load x tile: 16 k x 128 pixels (coalesced float4)
        #pragma unroll
        for (int i = 0; i < 2; i++) {
            int lin = t * 2 + i;                   // 0..511
            int kk  = lin >> 5;                    // 0..15
            int p4  = lin & 31;                    // float4 column
            *(float4*)&sX[kk][p4*4] =
                *(const float4*)(xb + (size_t)(k0 + kk) * HWp + p4 * 4);
        }
        __syncthreads();

        #pragma unroll
        for (int kk = 0; kk < 16; kk++) {
            float wf[8], xf[8];
            #pragma unroll
            for (int i = 0; i < 8; i++) wf[i] = sW[kk][ty*8 + i];
            #pragma unroll
            for (int j = 0; j < 8; j++) xf[j] = sX[kk][tx*8 + j];
            #pragma unroll
            for (int i = 0; i < 8; i++)
                #pragma unroll
                for (int j = 0; j < 8; j++)
                    acc[i][j] = fmaf(wf[i], xf[j], acc[i][j]);
        }
        __syncthreads();
    }

    // Epilogue: bias (+ReLU for key half), write to scratch
    #pragma unroll
    for (int i = 0; i < 8; i++) {
        int o = ty*8 + i;
        if (o < 64) {
            float bias = k1b[o];
            float* dst = g_k1 + ((size_t)b * CKV + o) * HWp + hw0 + tx*8;
            #pragma unroll
            for (int j = 0; j < 8; j++) dst[j] = fmaxf(acc[i][j] + bias, 0.f);
        } else {
            float bias = vb[o - 64];
            float* dst = g_v + ((size_t)b * CKV + (o - 64)) * HWp + hw0 + tx*8;
            #pragma unroll
            for (int j = 0; j < 8; j++) dst[j] = acc[i][j] + bias;
        }
    }
}

// ---------------------------------------------------------------------------
// Kernel 2: depthwise 3x3 (+bias) -> 1x1 conv 64->9 (+bias) -> softmax over taps
//   one thread per pixel; small weights cached in smem
//   grid = NPIX/256 = 288, block = 256
// ---------------------------------------------------------------------------
__global__ __launch_bounds__(256) void weights_kernel(
    const float* __restrict__ kdw_w, const float* __restrict__ kdw_b,
    const float* __restrict__ k3w,   const float* __restrict__ k3b)
{
    __shared__ float s_dw[CKV * 9];
    __shared__ float s_db[CKV];
    __shared__ float s_w3[9 * CKV];
    __shared__ float s_b3[9];

    const int t = threadIdx.x;
    for (int i = t; i < CKV * 9; i += 256) { s_dw[i] = kdw_w[i]; s_w3[i] = k3w[i]; }
    if (t < CKV) s_db[t] = kdw_b[t];
    if (t < 9)   s_b3[t] = k3b[t];
    __syncthreads();

    const int gid = blockIdx.x * 256 + t;   // 0..NPIX-1
    const int b   = gid / HWp;
    const int hw  = gid % HWp;
    const int h   = hw / Ww;
    const int w   = hw % Ww;

    float logit[9];
    #pragma unroll
    for (int tt = 0; tt < 9; tt++) logit[tt] = s_b3[tt];

    const float* k1base = g_k1 + (size_t)b * CKV * HWp;
    for (int c = 0; c < CKV; c++) {
        const float* plane = k1base + (size_t)c * HWp;
        float dw = s_db[c];
        #pragma unroll
        for (int dy = 0; dy < 3; dy++) {
            int yy = h + dy - 1;
            if (yy < 0 || yy >= Hh) continue;
            #pragma unroll
            for (int dx = 0; dx < 3; dx++) {
                int xx = w + dx - 1;
                if (xx < 0 || xx >= Ww) continue;
                dw = fmaf(plane[yy * Ww + xx], s_dw[c*9 + dy*3 + dx], dw);
            }
        }
        #pragma unroll
        for (int tt = 0; tt < 9; tt++)
            logit[tt] = fmaf(s_w3[tt * CKV + c], dw, logit[tt]);
    }

    // softmax over the 9 taps
    float m = logit[0];
    #pragma unroll
    for (int tt = 1; tt < 9; tt++) m = fmaxf(m, logit[tt]);
    float e[9], s = 0.f;
    #pragma unroll
    for (int tt = 0; tt < 9; tt++) { e[tt] = __expf(logit[tt] - m); s += e[tt]; }
    float inv = 1.f / s;
    float* wsb = g_ws + (size_t)b * 9 * HWp + hw;
    #pragma unroll
    for (int tt = 0; tt < 9; tt++) wsb[(size_t)tt * HWp] = e[tt] * inv;
}

// ---------------------------------------------------------------------------
// Kernel 3a: y[b,c,hw] = sum_t ws[b,t,hw] * v[b,c, nbr_t(hw)]  (zero pad)
//   grid = B*CKV*HWp/256 = 18432, block = 256, coalesced over hw
// ---------------------------------------------------------------------------
__global__ __launch_bounds__(256) void y_kernel()
{
    const int gid = blockIdx.x * 256 + threadIdx.x;   // over B*CKV*HWp
    const int hw = gid % HWp;
    const int bc = gid / HWp;
    const int b  = bc / CKV;
    const int h  = hw / Ww;
    const int w  = hw % Ww;

    const float* ws  = g_ws + (size_t)b * 9 * HWp + hw;
    const float* vpl = g_v  + (size_t)bc * HWp;

    float acc = 0.f;
    #pragma unroll
    for (int dy = 0; dy < 3; dy++) {
        int yy = h + dy - 1;
        bool oky = (yy >= 0 && yy < Hh);
        #pragma unroll
        for (int dx = 0; dx < 3; dx++) {
            int xx = w + dx - 1;
            float vv = (oky && xx >= 0 && xx < Ww) ? vpl[yy * Ww + xx] : 0.f;
            acc = fmaf(ws[(size_t)(dy*3 + dx) * HWp], vv, acc);
        }
    }
    g_y[gid] = acc;
}

// ---------------------------------------------------------------------------
// Kernel 3b: out[b,co,hw] = x[b,co,hw] + out_b[co] + sum_c out_w[co,c]*y[b,c,hw]
//   128 co x 128 pixels per CTA, K=64 fully resident in smem
//   grid = (576, 4), block = 256
// ---------------------------------------------------------------------------
__global__ __launch_bounds__(256) void out_gemm(
    const float* __restrict__ x,
    const float* __restrict__ ow, const float* __restrict__ ob,
    float* __restrict__ out)
{
    __shared__ float sW[64][128];
    __shared__ float sY[64][128];

    const int pt  = blockIdx.x;
    const int b   = pt / 72;
    const int hw0 = (pt % 72) * 128;
    const int co0 = blockIdx.y * 128;
    const int t   = threadIdx.x;

    // Load out_w tile: 128 co x 64 k (2048 float4, 8 per thread), coalesced rows
    #pragma unroll
    for (int i = 0; i < 8; i++) {
        int lin = t * 8 + i;              // 0..2047
        int o   = lin >> 4;               // 0..127
        int kq  = lin & 15;               // 16 float4 per 64-k row
        float4 w4 = *(const float4*)(ow + (size_t)(co0 + o) * CKV + kq * 4);
        sW[kq*4+0][o] = w4.x; sW[kq*4+1][o] = w4.y;
        sW[kq*4+2][o] = w4.z; sW[kq*4+3][o] = w4.w;
    }
    // Load y tile: 64 k x 128 pixels
    const float* yb = g_y + (size_t)b * CKV * HWp + hw0;
    #pragma unroll
    for (int i = 0; i < 8; i++) {
        int lin = t * 8 + i;
        int kk  = lin >> 5;
        int p4  = lin & 31;
        *(float4*)&sY[kk][p4*4] = *(const float4*)(yb + (size_t)kk * HWp + p4 * 4);
    }
    __syncthreads();

    const int ty = t >> 4;
    const int tx = t & 15;
    float acc[8][8];
    #pragma unroll
    for (int i = 0; i < 8; i++)
        #pragma unroll
        for (int j = 0; j < 8; j++) acc[i][j] = 0.f;

    #pragma unroll 16
    for (int kk = 0; kk < 64; kk++) {
        float wf[8], yf[8];
        #pragma unroll
        for (int i = 0; i < 8; i++) wf[i] = sW[kk][ty*8 + i];
        #pragma unroll
        for (int j = 0; j < 8; j++) yf[j] = sY[kk][tx*8 + j];
        #pragma unroll
        for (int i = 0; i < 8; i++)
            #pragma unroll
            for (int j = 0; j < 8; j++)
                acc[i][j] = fmaf(wf[i], yf[j], acc[i][j]);
    }

    // Epilogue: residual + bias
    #pragma unroll
    for (int i = 0; i < 8; i++) {
        int co = co0 + ty*8 + i;
        float bias = ob[co];
        const float* xr = x   + ((size_t)b * Cc + co) * HWp + hw0 + tx*8;
        float*       dr = out + ((size_t)b * Cc + co) * HWp + hw0 + tx*8;
        #pragma unroll
        for (int j = 0; j < 8; j++) dr[j] = xr[j] + bias + acc[i][j];
    }
}

// ---------------------------------------------------------------------------
extern "C" void kernel_launch(void* const* d_in, const int* in_sizes, int n_in,
                              void* d_out, int out_size)
{
    const float* x      = (const float*)d_in[0];
    const float* key1_w = (const float*)d_in[1];
    const float* key1_b = (const float*)d_in[2];
    const float* kdw_w  = (const float*)d_in[3];
    const float* kdw_b  = (const float*)d_in[4];
    const float* key3_w = (const float*)d_in[5];
    const float* key3_b = (const float*)d_in[6];
    const float* val_w  = (const float*)d_in[7];
    const float* val_b  = (const float*)d_in[8];
    const float* out_w  = (const float*)d_in[9];
    const float* out_b  = (const float*)d_in[10];
    float* out = (float*)d_out;

    k1v_gemm<<<NPIX / 128, 256>>>(x, key1_w, key1_b, val_w, val_b);
    weights_kernel<<<NPIX / 256, 256>>>(kdw_w, kdw_b, key3_w, key3_b);
    y_kernel<<<(Bz * CKV * HWp) / 256, 256>>>();
    out_gemm<<<dim3(NPIX / 128, Cc / 128), 256>>>(x, out_w, out_b, out);
}

// round 4
// speedup vs baseline: 2.0617x; 2.0617x over previous
#include <cuda_runtime.h>
#include <cstdint>

#define Bz   8
#define Cc   512
#define Hh   96
#define Ww   96
#define HWp  9216
#define NPIX (Bz * HWp)
#define CKV  64

// Scratch (device globals: allocation-free per harness rules)
__device__ float g_k1[Bz * CKV * HWp];
__device__ float g_v [Bz * CKV * HWp];
__device__ float g_ws[Bz * 9   * HWp];
__device__ float g_y [Bz * CKV * HWp];

// ---------------------------------------------------------------------------
// helpers
// ---------------------------------------------------------------------------
__device__ __forceinline__ uint32_t smem_u32(const void* p) {
    uint32_t a;
    asm("{ .reg .u64 t; cvta.to.shared.u64 t, %1; cvt.u32.u64 %0, t; }" : "=r"(a) : "l"(p));
    return a;
}
__device__ __forceinline__ uint32_t f2tf32(float f) {
    uint32_t r;
    asm("cvt.rna.tf32.f32 %0, %1;" : "=r"(r) : "f"(f));
    return r;
}
__device__ __forceinline__ void sts128(uint32_t a, uint32_t x, uint32_t y, uint32_t z, uint32_t w) {
    asm volatile("st.shared.v4.b32 [%0], {%1,%2,%3,%4};" :: "r"(a), "r"(x), "r"(y), "r"(z), "r"(w) : "memory");
}
__device__ __forceinline__ uint32_t lds32(uint32_t a) {
    uint32_t v;
    asm volatile("ld.shared.b32 %0, [%1];" : "=r"(v) : "r"(a));
    return v;
}
// Swizzled smem address: 128B rows (32 floats), 16B blocks XOR'd by row&7.
// Conflict-free for both the transposed STS.128 and the mma fragment LDS.
__device__ __forceinline__ uint32_t swaddr(uint32_t base, int row, int k) {
    return base + (uint32_t)(row * 128) + (uint32_t)((((k >> 2) ^ (row & 7)) << 4) + ((k & 3) << 2));
}
// D(16x8) += A(16x8,row) * B(8x8,col)  tf32
__device__ __forceinline__ void mma_tf32(float* d, const uint32_t* a, const uint32_t* b) {
    asm volatile(
        "mma.sync.aligned.m16n8k8.row.col.f32.tf32.tf32.f32 "
        "{%0,%1,%2,%3}, {%4,%5,%6,%7}, {%8,%9}, {%0,%1,%2,%3};"
        : "+f"(d[0]), "+f"(d[1]), "+f"(d[2]), "+f"(d[3])
        : "r"(a[0]), "r"(a[1]), "r"(a[2]), "r"(a[3]), "r"(b[0]), "r"(b[1]));
}

// ---------------------------------------------------------------------------
// Kernel 1: key1+value 1x1 convs. D[128ch][128pix], K=512, tf32 mma.sync.
//   grid = 576, block = 256 (8 warps, warp tile 64x32), dyn smem = 64KB
// ---------------------------------------------------------------------------
__global__ __launch_bounds__(256) void k1v_mma(
    const float* __restrict__ x,
    const float* __restrict__ k1w, const float* __restrict__ k1b,
    const float* __restrict__ vw,  const float* __restrict__ vb)
{
    extern __shared__ char smem[];
    const uint32_t sb = smem_u32(smem);

    const int t = threadIdx.x, warp = t >> 5, lane = t & 31;
    const int b = blockIdx.x / 72, hw0 = (blockIdx.x % 72) * 128;
    const float* xb = x + (size_t)b * Cc * HWp + hw0;

    // A-load mapping: row = t/2 (128 rows of weights), quads (t&1)*4 + i
    const int arow = t >> 1, aq0 = (t & 1) * 4;
    const float* awsrc = (arow < 64) ? (k1w + (size_t)arow * Cc)
                                     : (vw  + (size_t)(arow - 64) * Cc);
    // B-load mapping: pixel p = t%128, quads (t/128)*4 + i (transpose store)
    const int bp = t & 127, bq0 = (t >> 7) * 4;

    // warp tiles: wm in {0,64}, wn in {0,32,64,96}
    const int wm = (warp & 1) * 64, wn = (warp >> 1) * 32;

    float acc[4][4][4];
    #pragma unroll
    for (int i = 0; i < 4; i++)
        #pragma unroll
        for (int j = 0; j < 4; j++)
            #pragma unroll
            for (int q = 0; q < 4; q++) acc[i][j][q] = 0.f;

    float pa[16], pb[16];

    auto loadA = [&](int k0) {
        #pragma unroll
        for (int i = 0; i < 4; i++) {
            float4 v = *(const float4*)(awsrc + k0 + (aq0 + i) * 4);
            pa[i*4+0] = v.x; pa[i*4+1] = v.y; pa[i*4+2] = v.z; pa[i*4+3] = v.w;
        }
    };
    auto loadB = [&](int k0) {
        #pragma unroll
        for (int i = 0; i < 4; i++) {
            const float* s = xb + (size_t)(k0 + (bq0 + i) * 4) * HWp + bp;
            pb[i*4+0] = s[0]; pb[i*4+1] = s[HWp]; pb[i*4+2] = s[2*HWp]; pb[i*4+3] = s[3*HWp];
        }
    };
    auto store = [&](int buf) {
        uint32_t sA = sb + (uint32_t)buf * 32768u;
        uint32_t sB = sA + 16384u;
        #pragma unroll
        for (int i = 0; i < 4; i++) {
            sts128(swaddr(sA, arow, (aq0 + i) * 4),
                   f2tf32(pa[i*4+0]), f2tf32(pa[i*4+1]), f2tf32(pa[i*4+2]), f2tf32(pa[i*4+3]));
            sts128(swaddr(sB, bp, (bq0 + i) * 4),
                   f2tf32(pb[i*4+0]), f2tf32(pb[i*4+1]), f2tf32(pb[i*4+2]), f2tf32(pb[i*4+3]));
        }
    };
    auto compute = [&](int buf) {
        uint32_t sA = sb + (uint32_t)buf * 32768u;
        uint32_t sB = sA + 16384u;
        #pragma unroll
        for (int ks = 0; ks < 4; ks++) {
            const int kb = ks * 8;
            uint32_t af[4][4], bf[4][2];
            #pragma unroll
            for (int mi = 0; mi < 4; mi++) {
                int r = wm + mi * 16 + (lane >> 2);
                int c = kb + (lane & 3);
                af[mi][0] = lds32(swaddr(sA, r,     c));
                af[mi][1] = lds32(swaddr(sA, r + 8, c));
                af[mi][2] = lds32(swaddr(sA, r,     c + 4));
                af[mi][3] = lds32(swaddr(sA, r + 8, c + 4));
            }
            #pragma unroll
            for (int ni = 0; ni < 4; ni++) {
                int n = wn + ni * 8 + (lane >> 2);
                int c = kb + (lane & 3);
                bf[ni][0] = lds32(swaddr(sB, n, c));
                bf[ni][1] = lds32(swaddr(sB, n, c + 4));
            }
            #pragma unroll
            for (int mi = 0; mi < 4; mi++)
                #pragma unroll
                for (int ni = 0; ni < 4; ni++)
                    mma_tf32(acc[mi][ni], af[mi], bf[ni]);
        }
    };

    loadA(0); loadB(0); store(0);
    __syncthreads();
    for (int ck = 0; ck < 16; ck++) {
        if (ck < 15) { loadA((ck + 1) * 32); loadB((ck + 1) * 32); }
        compute(ck & 1);
        if (ck < 15) store((ck + 1) & 1);
        __syncthreads();
    }

    // Epilogue: bias (+ReLU on key half), direct float2 stores
    const bool iskey = (wm == 0);
    float* basep = iskey ? (g_k1 + (size_t)b * CKV * HWp) : (g_v + (size_t)b * CKV * HWp);
    #pragma unroll
    for (int mi = 0; mi < 4; mi++) {
        #pragma unroll
        for (int h = 0; h < 2; h++) {
            const int ch = mi * 16 + (lane >> 2) + h * 8;   // channel within 64
            const float bias = iskey ? k1b[ch] : vb[ch];
            #pragma unroll
            for (int ni = 0; ni < 4; ni++) {
                const int n0 = hw0 + wn + ni * 8 + (lane & 3) * 2;
                float v0 = acc[mi][ni][h*2+0] + bias;
                float v1 = acc[mi][ni][h*2+1] + bias;
                if (iskey) { v0 = fmaxf(v0, 0.f); v1 = fmaxf(v1, 0.f); }
                float2 o = make_float2(v0, v1);
                *(float2*)(basep + (size_t)ch * HWp + n0) = o;
            }
        }
    }
}

// ---------------------------------------------------------------------------
// Kernel 2: depthwise 3x3 -> 1x1 64->9 -> softmax (unchanged)
// ---------------------------------------------------------------------------
__global__ __launch_bounds__(256) void weights_kernel(
    const float* __restrict__ kdw_w, const float* __restrict__ kdw_b,
    const float* __restrict__ k3w,   const float* __restrict__ k3b)
{
    __shared__ float s_dw[CKV * 9];
    __shared__ float s_db[CKV];
    __shared__ float s_w3[9 * CKV];
    __shared__ float s_b3[9];

    const int t = threadIdx.x;
    for (int i = t; i < CKV * 9; i += 256) { s_dw[i] = kdw_w[i]; s_w3[i] = k3w[i]; }
    if (t < CKV) s_db[t] = kdw_b[t];
    if (t < 9)   s_b3[t] = k3b[t];
    __syncthreads();

    const int gid = blockIdx.x * 256 + t;
    const int b  = gid / HWp;
    const int hw = gid % HWp;
    const int h  = hw / Ww;
    const int w  = hw % Ww;

    float logit[9];
    #pragma unroll
    for (int tt = 0; tt < 9; tt++) logit[tt] = s_b3[tt];

    const float* k1base = g_k1 + (size_t)b * CKV * HWp;
    for (int c = 0; c < CKV; c++) {
        const float* plane = k1base + (size_t)c * HWp;
        float dw = s_db[c];
        #pragma unroll
        for (int dy = 0; dy < 3; dy++) {
            int yy = h + dy - 1;
            if (yy < 0 || yy >= Hh) continue;
            #pragma unroll
            for (int dx = 0; dx < 3; dx++) {
                int xx = w + dx - 1;
                if (xx < 0 || xx >= Ww) continue;
                dw = fmaf(plane[yy * Ww + xx], s_dw[c * 9 + dy * 3 + dx], dw);
            }
        }
        #pragma unroll
        for (int tt = 0; tt < 9; tt++)
            logit[tt] = fmaf(s_w3[tt * CKV + c], dw, logit[tt]);
    }

    float m = logit[0];
    #pragma unroll
    for (int tt = 1; tt < 9; tt++) m = fmaxf(m, logit[tt]);
    float e[9], s = 0.f;
    #pragma unroll
    for (int tt = 0; tt < 9; tt++) { e[tt] = __expf(logit[tt] - m); s += e[tt]; }
    float inv = 1.f / s;
    float* wsb = g_ws + (size_t)b * 9 * HWp + hw;
    #pragma unroll
    for (int tt = 0; tt < 9; tt++) wsb[(size_t)tt * HWp] = e[tt] * inv;
}

// ---------------------------------------------------------------------------
// Kernel 3: weighted neighborhood gather (unchanged)
// ---------------------------------------------------------------------------
__global__ __launch_bounds__(256) void y_kernel()
{
    const int gid = blockIdx.x * 256 + threadIdx.x;
    const int hw = gid % HWp;
    const int bc = gid / HWp;
    const int b  = bc / CKV;
    const int h  = hw / Ww;
    const int w  = hw % Ww;

    const float* ws  = g_ws + (size_t)b * 9 * HWp + hw;
    const float* vpl = g_v  + (size_t)bc * HWp;

    float acc = 0.f;
    #pragma unroll
    for (int dy = 0; dy < 3; dy++) {
        int yy = h + dy - 1;
        bool oky = (yy >= 0 && yy < Hh);
        #pragma unroll
        for (int dx = 0; dx < 3; dx++) {
            int xx = w + dx - 1;
            float vv = (oky && xx >= 0 && xx < Ww) ? vpl[yy * Ww + xx] : 0.f;
            acc = fmaf(ws[(size_t)(dy * 3 + dx) * HWp], vv, acc);
        }
    }
    g_y[gid] = acc;
}

// ---------------------------------------------------------------------------
// Kernel 4: out 1x1 conv (512 co) + residual. D[128co][128pix], K=64, tf32 mma.
//   grid = (576, 4), block = 256, dyn smem = 64KB
// ---------------------------------------------------------------------------
__global__ __launch_bounds__(256) void out_mma(
    const float* __restrict__ x,
    const float* __restrict__ ow, const float* __restrict__ ob,
    float* __restrict__ out)
{
    extern __shared__ char smem[];
    const uint32_t sb = smem_u32(smem);

    const int t = threadIdx.x, warp = t >> 5, lane = t & 31;
    const int b = blockIdx.x / 72, hw0 = (blockIdx.x % 72) * 128;
    const int co0 = blockIdx.y * 128;
    const float* yb = g_y + (size_t)b * CKV * HWp + hw0;

    const int arow = t >> 1, aq0 = (t & 1) * 4;
    const float* awsrc = ow + (size_t)(co0 + arow) * CKV;
    const int bp = t & 127, bq0 = (t >> 7) * 4;
    const int wm = (warp & 1) * 64, wn = (warp >> 1) * 32;

    float acc[4][4][4];
    #pragma unroll
    for (int i = 0; i < 4; i++)
        #pragma unroll
        for (int j = 0; j < 4; j++)
            #pragma unroll
            for (int q = 0; q < 4; q++) acc[i][j][q] = 0.f;

    float pa[16], pb[16];
    auto loadA = [&](int k0) {
        #pragma unroll
        for (int i = 0; i < 4; i++) {
            float4 v = *(const float4*)(awsrc + k0 + (aq0 + i) * 4);
            pa[i*4+0] = v.x; pa[i*4+1] = v.y; pa[i*4+2] = v.z; pa[i*4+3] = v.w;
        }
    };
    auto loadB = [&](int k0) {
        #pragma unroll
        for (int i = 0; i < 4; i++) {
            const float* s = yb + (size_t)(k0 + (bq0 + i) * 4) * HWp + bp;
            pb[i*4+0] = s[0]; pb[i*4+1] = s[HWp]; pb[i*4+2] = s[2*HWp]; pb[i*4+3] = s[3*HWp];
        }
    };
    auto store = [&](int buf) {
        uint32_t sA = sb + (uint32_t)buf * 32768u;
        uint32_t sB = sA + 16384u;
        #pragma unroll
        for (int i = 0; i < 4; i++) {
            sts128(swaddr(sA, arow, (aq0 + i) * 4),
                   f2tf32(pa[i*4+0]), f2tf32(pa[i*4+1]), f2tf32(pa[i*4+2]), f2tf32(pa[i*4+3]));
            sts128(swaddr(sB, bp, (bq0 + i) * 4),
                   f2tf32(pb[i*4+0]), f2tf32(pb[i*4+1]), f2tf32(pb[i*4+2]), f2tf32(pb[i*4+3]));
        }
    };
    auto compute = [&](int buf) {
        uint32_t sA = sb + (uint32_t)buf * 32768u;
        uint32_t sB = sA + 16384u;
        #pragma unroll
        for (int ks = 0; ks < 4; ks++) {
            const int kb = ks * 8;
            uint32_t af[4][4], bf[4][2];
            #pragma unroll
            for (int mi = 0; mi < 4; mi++) {
                int r = wm + mi * 16 + (lane >> 2);
                int c = kb + (lane & 3);
                af[mi][0] = lds32(swaddr(sA, r,     c));
                af[mi][1] = lds32(swaddr(sA, r + 8, c));
                af[mi][2] = lds32(swaddr(sA, r,     c + 4));
                af[mi][3] = lds32(swaddr(sA, r + 8, c + 4));
            }
            #pragma unroll
            for (int ni = 0; ni < 4; ni++) {
                int n = wn + ni * 8 + (lane >> 2);
                int c = kb + (lane & 3);
                bf[ni][0] = lds32(swaddr(sB, n, c));
                bf[ni][1] = lds32(swaddr(sB, n, c + 4));
            }
            #pragma unroll
            for (int mi = 0; mi < 4; mi++)
                #pragma unroll
                for (int ni = 0; ni < 4; ni++)
                    mma_tf32(acc[mi][ni], af[mi], bf[ni]);
        }
    };

    loadA(0); loadB(0); store(0);
    __syncthreads();
    for (int ck = 0; ck < 2; ck++) {
        if (ck < 1) { loadA(32); loadB(32); }
        compute(ck & 1);
        if (ck < 1) store(1);
        __syncthreads();
    }

    // Epilogue: residual + bias, direct float2 stores
    #pragma unroll
    for (int mi = 0; mi < 4; mi++) {
        #pragma unroll
        for (int h = 0; h < 2; h++) {
            const int co = co0 + wm + mi * 16 + (lane >> 2) + h * 8;
            const float bias = ob[co];
            #pragma unroll
            for (int ni = 0; ni < 4; ni++) {
                const int n0 = hw0 + wn + ni * 8 + (lane & 3) * 2;
                const size_t idx = ((size_t)b * Cc + co) * HWp + n0;
                float2 xv = *(const float2*)(x + idx);
                float2 o;
                o.x = xv.x + bias + acc[mi][ni][h*2+0];
                o.y = xv.y + bias + acc[mi][ni][h*2+1];
                *(float2*)(out + idx) = o;
            }
        }
    }
}

// ---------------------------------------------------------------------------
extern "C" void kernel_launch(void* const* d_in, const int* in_sizes, int n_in,
                              void* d_out, int out_size)
{
    const float* x      = (const float*)d_in[0];
    const float* key1_w = (const float*)d_in[1];
    const float* key1_b = (const float*)d_in[2];
    const float* kdw_w  = (const float*)d_in[3];
    const float* kdw_b  = (const float*)d_in[4];
    const float* key3_w = (const float*)d_in[5];
    const float* key3_b = (const float*)d_in[6];
    const float* val_w  = (const float*)d_in[7];
    const float* val_b  = (const float*)d_in[8];
    const float* out_w  = (const float*)d_in[9];
    const float* out_b  = (const float*)d_in[10];
    float* out = (float*)d_out;

    static bool attr_set = false;
    if (!attr_set) {
        cudaFuncSetAttribute(k1v_mma, cudaFuncAttributeMaxDynamicSharedMemorySize, 65536);
        cudaFuncSetAttribute(out_mma, cudaFuncAttributeMaxDynamicSharedMemorySize, 65536);
        attr_set = true;
    }

    k1v_mma<<<576, 256, 65536>>>(x, key1_w, key1_b, val_w, val_b);
    weights_kernel<<<NPIX / 256, 256>>>(kdw_w, kdw_b, key3_w, key3_b);
    y_kernel<<<(Bz * CKV * HWp) / 256, 256>>>();
    out_mma<<<dim3(576, 4), 256, 65536>>>(x, out_w, out_b, out);
}